// round 3
// baseline (speedup 1.0000x reference)
#include <cuda_runtime.h>
#include <cstdint>

#define N_TOKENS 4096
#define D_IN     4096
#define D_HIDDEN 32768
#define TOPK     64

// Scratch (device globals: allocation-free at launch time).
__device__ float g_wdecT[(size_t)D_HIDDEN * D_IN];   // 512 MB, W_dec transposed [h][d]
__device__ int   g_topk_idx[N_TOKENS * TOPK];
__device__ float g_topk_val[N_TOKENS * TOPK];

// ---------------------------------------------------------------------------
// Encode: pre[n,h] = relu( sum_d x[n,d]*W_enc[h,d] + b_enc[h] )
// Kahan-compensated fp32 accumulation (error ~1e-7 instead of ~1.6e-6) so the
// top-64 selection matches the reference's ranking exactly (no boundary swaps).
// Products are taken in pairs (k, k+1) via one FMUL+FFMA, then one compensated
// add: 3 pipe-ops per MAC. All compensation steps use _rn intrinsics so the
// compiler cannot re-associate or contract them away.
// 128x128 block tile, BK=16, 256 threads, 8x8 per thread.
// ---------------------------------------------------------------------------
#define BM 128
#define BN 128
#define BK 16

__global__ __launch_bounds__(256, 1)
void encode_kernel(const float* __restrict__ x,
                   const float* __restrict__ W,
                   const float* __restrict__ bias,
                   float* __restrict__ pre_out)
{
    __shared__ float As[BK][BM];   // [k][n]
    __shared__ float Bs[BK][BN];   // [k][h]

    const int tid = threadIdx.x;
    const int bn = blockIdx.y * BM;   // token offset
    const int bh = blockIdx.x * BN;   // hidden offset
    const int tr = tid / 16;          // 0..15 -> token sub-tile
    const int tc = tid % 16;          // 0..15 -> hidden sub-tile

    float s[8][8];   // Kahan sum
    float c[8][8];   // Kahan compensation
#pragma unroll
    for (int i = 0; i < 8; ++i)
#pragma unroll
        for (int j = 0; j < 8; ++j) { s[i][j] = 0.0f; c[i][j] = 0.0f; }

    for (int k0 = 0; k0 < D_IN; k0 += BK) {
        // Load A tile: 128 rows x 16 k (512 float4, 2 per thread), transposed store
#pragma unroll
        for (int l = 0; l < 2; ++l) {
            int q   = l * 256 + tid;      // 0..511
            int row = q >> 2;             // 0..127
            int c4  = q & 3;              // 0..3
            float4 v = *(const float4*)(x + (size_t)(bn + row) * D_IN + k0 + c4 * 4);
            As[c4 * 4 + 0][row] = v.x;
            As[c4 * 4 + 1][row] = v.y;
            As[c4 * 4 + 2][row] = v.z;
            As[c4 * 4 + 3][row] = v.w;
        }
        // Load B tile (W_enc rows are K-major too)
#pragma unroll
        for (int l = 0; l < 2; ++l) {
            int q   = l * 256 + tid;
            int row = q >> 2;
            int c4  = q & 3;
            float4 v = *(const float4*)(W + (size_t)(bh + row) * D_IN + k0 + c4 * 4);
            Bs[c4 * 4 + 0][row] = v.x;
            Bs[c4 * 4 + 1][row] = v.y;
            Bs[c4 * 4 + 2][row] = v.z;
            Bs[c4 * 4 + 3][row] = v.w;
        }
        __syncthreads();

#pragma unroll
        for (int kk = 0; kk < BK; kk += 2) {
            float a0[8], a1[8], b0[8], b1[8];
            *(float4*)&a0[0] = *(const float4*)&As[kk][tr * 8];
            *(float4*)&a0[4] = *(const float4*)&As[kk][tr * 8 + 4];
            *(float4*)&a1[0] = *(const float4*)&As[kk + 1][tr * 8];
            *(float4*)&a1[4] = *(const float4*)&As[kk + 1][tr * 8 + 4];
            *(float4*)&b0[0] = *(const float4*)&Bs[kk][tc * 8];
            *(float4*)&b0[4] = *(const float4*)&Bs[kk][tc * 8 + 4];
            *(float4*)&b1[0] = *(const float4*)&Bs[kk + 1][tc * 8];
            *(float4*)&b1[4] = *(const float4*)&Bs[kk + 1][tc * 8 + 4];
#pragma unroll
            for (int i = 0; i < 8; ++i) {
#pragma unroll
                for (int j = 0; j < 8; ++j) {
                    // pair of products
                    float t = __fmaf_rn(a1[i], b1[j], __fmul_rn(a0[i], b0[j]));
                    // Kahan compensated add of t into s[i][j]
                    float y = __fsub_rn(t, c[i][j]);
                    float u = __fadd_rn(s[i][j], y);
                    c[i][j] = __fsub_rn(__fsub_rn(u, s[i][j]), y);
                    s[i][j] = u;
                }
            }
        }
        __syncthreads();
    }

    // Epilogue: + bias, ReLU, store
#pragma unroll
    for (int i = 0; i < 8; ++i) {
        int n = bn + tr * 8 + i;
        float* out_row = pre_out + (size_t)n * D_HIDDEN + bh + tc * 8;
#pragma unroll
        for (int j = 0; j < 8; ++j) {
            float v = __fadd_rn(s[i][j], bias[bh + tc * 8 + j]);
            out_row[j] = v > 0.0f ? v : 0.0f;
        }
    }
}

// ---------------------------------------------------------------------------
// Top-k per token (k=64) via 4-pass 8-bit radix select on float bits.
// All values are >= 0 post-ReLU, so uint bit order == value order.
// Ties at the k-th value resolved by smallest index (jax.lax.top_k semantics).
// Masks the row IN PLACE (row lives in d_out features region) and emits
// compact (idx,val) pairs for the sparse decode.
// ---------------------------------------------------------------------------
__global__ __launch_bounds__(256)
void topk_kernel(float* __restrict__ feat)
{
    const int n   = blockIdx.x;
    const int tid = threadIdx.x;
    float* row = feat + (size_t)n * D_HIDDEN;

    __shared__ unsigned hist[256];
    __shared__ unsigned s_prefix, s_kth, s_cgt;
    __shared__ int      s_eq_idx[256];
    __shared__ int      s_eq_cnt;
    __shared__ int      s_cutoff;
    __shared__ int      s_out_cnt;

    unsigned prefix = 0, hi_mask = 0;
    int kth = TOPK;     // rank to find within current prefix class
    int cgt = 0;        // count strictly greater than current prefix class top

    for (int pass = 0; pass < 4; ++pass) {
        const int shift = 24 - pass * 8;
        hist[tid] = 0;
        __syncthreads();

        for (int i = tid; i < D_HIDDEN; i += 256) {
            unsigned bits = __float_as_uint(row[i]);
            if ((bits & hi_mask) == prefix)
                atomicAdd(&hist[(bits >> shift) & 0xFF], 1u);
        }
        __syncthreads();

        if (tid == 0) {
            int cum = 0, b = 255;
            for (; b >= 0; --b) {
                cum += (int)hist[b];
                if (cum >= kth) break;
            }
            int above = cum - (int)hist[b];
            s_prefix = prefix | ((unsigned)b << shift);
            s_kth    = (unsigned)(kth - above);
            s_cgt    = (unsigned)(cgt + above);
        }
        __syncthreads();
        prefix  = s_prefix;
        kth     = (int)s_kth;
        cgt     = (int)s_cgt;
        hi_mask |= (0xFFu << shift);
        __syncthreads();   // hist reuse next pass
    }

    const unsigned tbits = prefix;         // bits of k-th largest value
    const int extra = TOPK - cgt;          // #equal-to-t entries to keep (>=1)

    // Collect indices of elements equal to t
    if (tid == 0) s_eq_cnt = 0;
    __syncthreads();
    for (int i = tid; i < D_HIDDEN; i += 256) {
        if (__float_as_uint(row[i]) == tbits) {
            int p = atomicAdd(&s_eq_cnt, 1);
            if (p < 256) s_eq_idx[p] = i;
        }
    }
    __syncthreads();

    if (tid == 0) {
        int m = s_eq_cnt < 256 ? s_eq_cnt : 256;
        // insertion sort ascending (m is tiny in practice)
        for (int a = 1; a < m; ++a) {
            int key = s_eq_idx[a], b = a - 1;
            while (b >= 0 && s_eq_idx[b] > key) { s_eq_idx[b + 1] = s_eq_idx[b]; --b; }
            s_eq_idx[b + 1] = key;
        }
        int e = extra < m ? extra : m;
        s_cutoff  = s_eq_idx[e - 1];   // keep equals with index <= cutoff
        s_out_cnt = 0;
    }
    __syncthreads();
    const int cutoff = s_cutoff;

    // Mask row in place + emit compact pairs
    for (int i = tid; i < D_HIDDEN; i += 256) {
        float v = row[i];
        unsigned bits = __float_as_uint(v);
        bool sel = (bits > tbits) || (bits == tbits && i <= cutoff);
        row[i] = sel ? v : 0.0f;
        if (sel) {
            int p = atomicAdd(&s_out_cnt, 1);
            if (p < TOPK) {
                g_topk_idx[n * TOPK + p] = i;
                g_topk_val[n * TOPK + p] = v;
            }
        }
    }
}

// ---------------------------------------------------------------------------
// Transpose W_dec [D_IN, D_HIDDEN] -> g_wdecT [D_HIDDEN, D_IN]
// ---------------------------------------------------------------------------
__global__ __launch_bounds__(256)
void transpose_kernel(const float* __restrict__ W)
{
    __shared__ float t[32][33];
    const int h0 = blockIdx.x * 32;
    const int d0 = blockIdx.y * 32;
    const int tx = threadIdx.x;   // 0..31
    const int ty = threadIdx.y;   // 0..7

#pragma unroll
    for (int i = 0; i < 32; i += 8)
        t[ty + i][tx] = W[(size_t)(d0 + ty + i) * D_HIDDEN + h0 + tx];
    __syncthreads();
#pragma unroll
    for (int i = 0; i < 32; i += 8)
        g_wdecT[(size_t)(h0 + ty + i) * D_IN + d0 + tx] = t[tx][ty + i];
}

// ---------------------------------------------------------------------------
// Sparse decode: recon[n,:] = b_dec + sum_j val_j * W_decT[idx_j, :]
// One block per token, 256 threads, 16 register accumulators each.
// ---------------------------------------------------------------------------
__global__ __launch_bounds__(256)
void decode_kernel(float* __restrict__ recon, const float* __restrict__ b_dec)
{
    const int n   = blockIdx.x;
    const int tid = threadIdx.x;

    __shared__ int   s_idx[TOPK];
    __shared__ float s_val[TOPK];
    if (tid < TOPK) {
        s_idx[tid] = g_topk_idx[n * TOPK + tid];
        s_val[tid] = g_topk_val[n * TOPK + tid];
    }
    __syncthreads();

    float acc[16];
#pragma unroll
    for (int r = 0; r < 16; ++r) acc[r] = b_dec[tid + r * 256];

    for (int j = 0; j < TOPK; ++j) {
        const float* wr = g_wdecT + (size_t)s_idx[j] * D_IN;
        const float  v  = s_val[j];
#pragma unroll
        for (int r = 0; r < 16; ++r)
            acc[r] += v * wr[tid + r * 256];
    }

    float* out = recon + (size_t)n * D_IN;
#pragma unroll
    for (int r = 0; r < 16; ++r) out[tid + r * 256] = acc[r];
}

// ---------------------------------------------------------------------------
// Launch
// ---------------------------------------------------------------------------
extern "C" void kernel_launch(void* const* d_in, const int* in_sizes, int n_in,
                              void* d_out, int out_size)
{
    const float* x     = (const float*)d_in[0];
    const float* W_enc = (const float*)d_in[1];
    const float* b_enc = (const float*)d_in[2];
    const float* W_dec = (const float*)d_in[3];
    const float* b_dec = (const float*)d_in[4];

    float* recon = (float*)d_out;                                  // [4096, 4096]
    float* feat  = (float*)d_out + (size_t)N_TOKENS * D_IN;        // [4096, 32768]

    // Transpose W_dec (independent of encode; runs first on the stream)
    transpose_kernel<<<dim3(D_HIDDEN / 32, D_IN / 32), dim3(32, 8)>>>(W_dec);

    // Encode GEMM (Kahan fp32) + bias + ReLU -> feat region (acts as `pre` scratch)
    encode_kernel<<<dim3(D_HIDDEN / BN, N_TOKENS / BM), 256>>>(x, W_enc, b_enc, feat);

    // Per-token top-64 mask (in place) + compact pairs
    topk_kernel<<<N_TOKENS, 256>>>(feat);

    // Sparse decode -> recon
    decode_kernel<<<N_TOKENS, 256>>>(recon, b_dec);
}

// round 5
// speedup vs baseline: 11.7248x; 11.7248x over previous
#include <cuda_runtime.h>
#include <cuda_bf16.h>
#include <cstdint>

#define N_TOKENS 4096
#define D_IN     4096
#define D_HIDDEN 32768
#define TOPK     64
#define MARGIN   1e-3f

// ---------------- device scratch (no allocations allowed) -------------------
__device__ __nv_bfloat16 g_x1[(size_t)N_TOKENS * D_IN];
__device__ __nv_bfloat16 g_x2[(size_t)N_TOKENS * D_IN];
__device__ __nv_bfloat16 g_w1[(size_t)D_HIDDEN * D_IN];
__device__ __nv_bfloat16 g_w2[(size_t)D_HIDDEN * D_IN];
__device__ float g_wdecT[(size_t)D_HIDDEN * D_IN];
__device__ int   g_topk_idx[N_TOKENS * TOPK];
__device__ float g_topk_val[N_TOKENS * TOPK];
__device__ int   g_cand_idx[N_TOKENS * 64];
__device__ float g_cand_val[N_TOKENS * 64];
__device__ int   g_ndef[N_TOKENS];
__device__ int   g_ncand[N_TOKENS];

// ---------------- helpers ----------------------------------------------------
__device__ __forceinline__ uint32_t smem_u32(const void* p) {
    uint32_t a;
    asm("{ .reg .u64 t; cvta.to.shared.u64 t, %1; cvt.u32.u64 %0, t; }" : "=r"(a) : "l"(p));
    return a;
}
__device__ __forceinline__ void cp16(uint32_t saddr, const void* gaddr) {
    asm volatile("cp.async.cg.shared.global [%0], [%1], 16;" :: "r"(saddr), "l"(gaddr));
}
#define CP_COMMIT()  asm volatile("cp.async.commit_group;" ::: "memory")
#define CP_WAIT0()   asm volatile("cp.async.wait_group 0;" ::: "memory")

#define LDSM_X4(d, addr) \
    asm volatile("ldmatrix.sync.aligned.m8n8.x4.shared.b16 {%0,%1,%2,%3}, [%4];" \
        : "=r"((d)[0]), "=r"((d)[1]), "=r"((d)[2]), "=r"((d)[3]) : "r"(addr))
#define LDSM_X2(d, addr) \
    asm volatile("ldmatrix.sync.aligned.m8n8.x2.shared.b16 {%0,%1}, [%2];" \
        : "=r"((d)[0]), "=r"((d)[1]) : "r"(addr))

__device__ __forceinline__ void mma16816(float* d, const uint32_t* a, const uint32_t* b) {
    asm volatile("mma.sync.aligned.m16n8k16.row.col.f32.bf16.bf16.f32 "
        "{%0,%1,%2,%3}, {%4,%5,%6,%7}, {%8,%9}, {%0,%1,%2,%3};"
        : "+f"(d[0]), "+f"(d[1]), "+f"(d[2]), "+f"(d[3])
        : "r"(a[0]), "r"(a[1]), "r"(a[2]), "r"(a[3]), "r"(b[0]), "r"(b[1]));
}

// ---------------- split kernels (fp32 -> bf16 hi/lo) ------------------------
__global__ __launch_bounds__(256)
void split_x_kernel(const float* __restrict__ src)
{
    size_t i = ((size_t)blockIdx.x * 256 + threadIdx.x) * 4;
    if (i >= (size_t)N_TOKENS * D_IN) return;
    float4 v = *(const float4*)(src + i);
    float f[4] = {v.x, v.y, v.z, v.w};
    __nv_bfloat16 h1[4], h2[4];
#pragma unroll
    for (int j = 0; j < 4; ++j) {
        h1[j] = __float2bfloat16_rn(f[j]);
        h2[j] = __float2bfloat16_rn(f[j] - __bfloat162float(h1[j]));
    }
    *(__nv_bfloat162*)(g_x1 + i)     = __nv_bfloat162{h1[0], h1[1]};
    *(__nv_bfloat162*)(g_x1 + i + 2) = __nv_bfloat162{h1[2], h1[3]};
    *(__nv_bfloat162*)(g_x2 + i)     = __nv_bfloat162{h2[0], h2[1]};
    *(__nv_bfloat162*)(g_x2 + i + 2) = __nv_bfloat162{h2[2], h2[3]};
}

__global__ __launch_bounds__(256)
void split_w_kernel(const float* __restrict__ src)
{
    size_t i = ((size_t)blockIdx.x * 256 + threadIdx.x) * 4;
    if (i >= (size_t)D_HIDDEN * D_IN) return;
    float4 v = *(const float4*)(src + i);
    float f[4] = {v.x, v.y, v.z, v.w};
    __nv_bfloat16 h1[4], h2[4];
#pragma unroll
    for (int j = 0; j < 4; ++j) {
        h1[j] = __float2bfloat16_rn(f[j]);
        h2[j] = __float2bfloat16_rn(f[j] - __bfloat162float(h1[j]));
    }
    *(__nv_bfloat162*)(g_w1 + i)     = __nv_bfloat162{h1[0], h1[1]};
    *(__nv_bfloat162*)(g_w1 + i + 2) = __nv_bfloat162{h1[2], h1[3]};
    *(__nv_bfloat162*)(g_w2 + i)     = __nv_bfloat162{h2[0], h2[1]};
    *(__nv_bfloat162*)(g_w2 + i + 2) = __nv_bfloat162{h2[2], h2[3]};
}

// ---------------- encode: bf16x3-split GEMM on mma.sync ---------------------
// CTA tile 128(tok) x 128(hid), BK=64, 8 warps in 2x4, warp tile 64x32.
// SMEM stage: A1|A2|B1|B2, each 128 rows x 128B (XOR chunk swizzle), 64KB/stage,
// double-buffered via cp.async. 3 products (x1w1 + x1w2 + x2w1) per k16 step.
#define EBK 64
#define ARR_BYTES 16384
#define STAGE_BYTES (4 * ARR_BYTES)
#define ENC_SMEM (2 * STAGE_BYTES)
#define N_STAGES (D_IN / EBK)    // 64

__global__ __launch_bounds__(256, 1)
void encode_mma_kernel(const float* __restrict__ bias, float* __restrict__ feat)
{
    extern __shared__ __align__(128) char smem[];
    const int tid  = threadIdx.x;
    const int wid  = tid >> 5;
    const int lane = tid & 31;
    const int wm   = wid >> 2;       // 0..1
    const int wn   = wid & 3;        // 0..3
    const int bn   = blockIdx.x * 128;   // token tile (fastest-varying -> B tile L2-hot)
    const int bh   = blockIdx.y * 128;   // hidden tile
    const uint32_t smem_base = smem_u32(smem);

    float acc[4][4][4];
#pragma unroll
    for (int mt = 0; mt < 4; ++mt)
#pragma unroll
        for (int nt = 0; nt < 4; ++nt)
#pragma unroll
            for (int q = 0; q < 4; ++q) acc[mt][nt][q] = 0.0f;

#define PREFETCH(s) do {                                                          \
    const int _k0 = (s) * EBK;                                                    \
    const uint32_t _st = smem_base + ((s) & 1) * STAGE_BYTES;                     \
    _Pragma("unroll")                                                             \
    for (int _l = 0; _l < 4; ++_l) {                                              \
        int _id = _l * 256 + tid;                                                 \
        int _r = _id >> 3, _c = _id & 7;                                          \
        uint32_t _sw = (uint32_t)(_r * 128 + ((_c ^ (_r & 7)) << 4));             \
        size_t _ga = (size_t)(bn + _r) * D_IN + _k0 + _c * 8;                     \
        size_t _gb = (size_t)(bh + _r) * D_IN + _k0 + _c * 8;                     \
        cp16(_st + 0 * ARR_BYTES + _sw, g_x1 + _ga);                              \
        cp16(_st + 1 * ARR_BYTES + _sw, g_x2 + _ga);                              \
        cp16(_st + 2 * ARR_BYTES + _sw, g_w1 + _gb);                              \
        cp16(_st + 3 * ARR_BYTES + _sw, g_w2 + _gb);                              \
    }                                                                             \
    CP_COMMIT();                                                                  \
} while (0)

    PREFETCH(0);

    const int rA_base = wm * 64 + (lane & 15);
    const int rB_base = wn * 32 + (lane & 7);

    for (int s = 0; s < N_STAGES; ++s) {
        CP_WAIT0();
        __syncthreads();
        if (s + 1 < N_STAGES) PREFETCH(s + 1);
        const uint32_t st = smem_base + (s & 1) * STAGE_BYTES;

#pragma unroll
        for (int ks = 0; ks < 4; ++ks) {
            uint32_t a1[4][4], a2[4][4], b1[4][2], b2[4][2];
            const int cA = 2 * ks + (lane >> 4);
#pragma unroll
            for (int mt = 0; mt < 4; ++mt) {
                int r = rA_base + mt * 16;
                uint32_t off = st + (uint32_t)(r * 128 + ((cA ^ (r & 7)) << 4));
                LDSM_X4(a1[mt], off + 0 * ARR_BYTES);
                LDSM_X4(a2[mt], off + 1 * ARR_BYTES);
            }
            const int cB = 2 * ks + ((lane >> 3) & 1);
#pragma unroll
            for (int nt = 0; nt < 4; ++nt) {
                int r = rB_base + nt * 8;
                uint32_t off = st + (uint32_t)(r * 128 + ((cB ^ (r & 7)) << 4));
                LDSM_X2(b1[nt], off + 2 * ARR_BYTES);
                LDSM_X2(b2[nt], off + 3 * ARR_BYTES);
            }
#pragma unroll
            for (int mt = 0; mt < 4; ++mt) {
#pragma unroll
                for (int nt = 0; nt < 4; ++nt) {
                    mma16816(acc[mt][nt], a1[mt], b1[nt]);
                    mma16816(acc[mt][nt], a1[mt], b2[nt]);
                    mma16816(acc[mt][nt], a2[mt], b1[nt]);
                }
            }
        }
        __syncthreads();
    }
#undef PREFETCH

    // Epilogue: +bias, ReLU, store fp32
#pragma unroll
    for (int mt = 0; mt < 4; ++mt) {
        const int row0 = bn + wm * 64 + mt * 16 + (lane >> 2);
#pragma unroll
        for (int nt = 0; nt < 4; ++nt) {
            const int col0 = bh + wn * 32 + nt * 8 + (lane & 3) * 2;
            const float bb0 = bias[col0], bb1 = bias[col0 + 1];
            float2 v0, v1;
            v0.x = acc[mt][nt][0] + bb0; v0.x = v0.x > 0.0f ? v0.x : 0.0f;
            v0.y = acc[mt][nt][1] + bb1; v0.y = v0.y > 0.0f ? v0.y : 0.0f;
            v1.x = acc[mt][nt][2] + bb0; v1.x = v1.x > 0.0f ? v1.x : 0.0f;
            v1.y = acc[mt][nt][3] + bb1; v1.y = v1.y > 0.0f ? v1.y : 0.0f;
            *(float2*)&feat[(size_t)row0 * D_HIDDEN + col0]       = v0;
            *(float2*)&feat[(size_t)(row0 + 8) * D_HIDDEN + col0] = v1;
        }
    }
}

// ---------------- top-k: radix threshold + margin classification ------------
__global__ __launch_bounds__(256)
void topk_kernel(float* __restrict__ feat)
{
    const int n   = blockIdx.x;
    const int tid = threadIdx.x;
    float* row = feat + (size_t)n * D_HIDDEN;

    __shared__ unsigned hist[256];
    __shared__ unsigned s_prefix, s_kth;
    __shared__ int s_ndef, s_ncand;

    unsigned prefix = 0, hi_mask = 0;
    int kth = TOPK;

    for (int pass = 0; pass < 4; ++pass) {
        const int shift = 24 - pass * 8;
        hist[tid] = 0;
        __syncthreads();
        for (int i = tid; i < D_HIDDEN; i += 256) {
            unsigned bits = __float_as_uint(row[i]);
            if ((bits & hi_mask) == prefix)
                atomicAdd(&hist[(bits >> shift) & 0xFF], 1u);
        }
        __syncthreads();
        if (tid == 0) {
            int cum = 0, b = 255;
            for (; b >= 0; --b) { cum += (int)hist[b]; if (cum >= kth) break; }
            int above = cum - (int)hist[b];
            s_prefix = prefix | ((unsigned)b << shift);
            s_kth    = (unsigned)(kth - above);
        }
        __syncthreads();
        prefix = s_prefix;
        kth    = (int)s_kth;
        hi_mask |= (0xFFu << shift);
        __syncthreads();
    }

    const float thr = __uint_as_float(prefix);
    const float lo = thr - MARGIN, hi = thr + MARGIN;

    if (tid == 0) { s_ndef = 0; s_ncand = 0; }
    __syncthreads();

    for (int i = tid; i < D_HIDDEN; i += 256) {
        float v = row[i];
        if (v > hi) {
            int p = atomicAdd(&s_ndef, 1);
            g_topk_idx[n * TOPK + p] = i;
            g_topk_val[n * TOPK + p] = v;
        } else {
            if (v >= lo) {
                int q = atomicAdd(&s_ncand, 1);
                if (q < 64) { g_cand_idx[n * 64 + q] = i; g_cand_val[n * 64 + q] = v; }
            }
            row[i] = 0.0f;
        }
    }
    __syncthreads();
    if (tid == 0) {
        g_ndef[n]  = s_ndef;
        g_ncand[n] = s_ncand < 64 ? s_ncand : 64;
    }
}

// ---------------- rerank: exact fp64 scoring of boundary candidates ---------
__global__ __launch_bounds__(256)
void rerank_kernel(const float* __restrict__ x, const float* __restrict__ W_enc,
                   const float* __restrict__ b_enc, float* __restrict__ feat)
{
    __shared__ float  sx[D_IN];
    __shared__ double sred[256];
    __shared__ double s_exact[64];

    const int n   = blockIdx.x;
    const int tid = threadIdx.x;
    const int ndef  = g_ndef[n];
    const int ncand = g_ncand[n];
    const int need  = TOPK - ndef;
    float* row = feat + (size_t)n * D_HIDDEN;

    if (need <= 0) return;

    if (ncand <= need) {
        for (int c = tid; c < ncand; c += 256) {
            int idx = g_cand_idx[n * 64 + c];
            float v = g_cand_val[n * 64 + c];
            row[idx] = v;
            g_topk_idx[n * TOPK + ndef + c] = idx;
            g_topk_val[n * TOPK + ndef + c] = v;
        }
        return;
    }

    for (int i = tid * 4; i < D_IN; i += 1024)
        *(float4*)&sx[i] = *(const float4*)(x + (size_t)n * D_IN + i);
    __syncthreads();

    for (int c = 0; c < ncand; ++c) {
        const float* w = W_enc + (size_t)g_cand_idx[n * 64 + c] * D_IN;
        double acc = 0.0;
        for (int j = tid; j < D_IN; j += 256)
            acc += (double)sx[j] * (double)w[j];
        sred[tid] = acc;
        __syncthreads();
        for (int st = 128; st > 0; st >>= 1) {
            if (tid < st) sred[tid] += sred[tid + st];
            __syncthreads();
        }
        if (tid == 0) {
            double v = sred[0] + (double)b_enc[g_cand_idx[n * 64 + c]];
            s_exact[c] = v > 0.0 ? v : 0.0;
        }
        __syncthreads();
    }

    if (tid == 0) {
        bool used[64];
        for (int c = 0; c < ncand; ++c) used[c] = false;
        for (int r = 0; r < need; ++r) {
            int best = -1;
            for (int c = 0; c < ncand; ++c) {
                if (used[c]) continue;
                if (best < 0 || s_exact[c] > s_exact[best] ||
                    (s_exact[c] == s_exact[best] &&
                     g_cand_idx[n * 64 + c] < g_cand_idx[n * 64 + best]))
                    best = c;
            }
            used[best] = true;
            int idx = g_cand_idx[n * 64 + best];
            float v = g_cand_val[n * 64 + best];
            row[idx] = v;
            g_topk_idx[n * TOPK + ndef + r] = idx;
            g_topk_val[n * TOPK + ndef + r] = v;
        }
    }
}

// ---------------- transpose W_dec -> [h][d] ---------------------------------
__global__ __launch_bounds__(256)
void transpose_kernel(const float* __restrict__ W)
{
    __shared__ float t[32][33];
    const int h0 = blockIdx.x * 32;
    const int d0 = blockIdx.y * 32;
    const int tx = threadIdx.x;
    const int ty = threadIdx.y;
#pragma unroll
    for (int i = 0; i < 32; i += 8)
        t[ty + i][tx] = W[(size_t)(d0 + ty + i) * D_HIDDEN + h0 + tx];
    __syncthreads();
#pragma unroll
    for (int i = 0; i < 32; i += 8)
        g_wdecT[(size_t)(h0 + ty + i) * D_IN + d0 + tx] = t[tx][ty + i];
}

// ---------------- sparse decode ---------------------------------------------
__global__ __launch_bounds__(256)
void decode_kernel(float* __restrict__ recon, const float* __restrict__ b_dec)
{
    const int n   = blockIdx.x;
    const int tid = threadIdx.x;

    __shared__ int   s_idx[TOPK];
    __shared__ float s_val[TOPK];
    if (tid < TOPK) {
        s_idx[tid] = g_topk_idx[n * TOPK + tid];
        s_val[tid] = g_topk_val[n * TOPK + tid];
    }
    __syncthreads();

    float acc[16];
#pragma unroll
    for (int r = 0; r < 16; ++r) acc[r] = b_dec[tid + r * 256];

    for (int j = 0; j < TOPK; ++j) {
        const float* wr = g_wdecT + (size_t)s_idx[j] * D_IN;
        const float  v  = s_val[j];
#pragma unroll
        for (int r = 0; r < 16; ++r)
            acc[r] += v * wr[tid + r * 256];
    }

    float* out = recon + (size_t)n * D_IN;
#pragma unroll
    for (int r = 0; r < 16; ++r) out[tid + r * 256] = acc[r];
}

// ---------------- launch -----------------------------------------------------
extern "C" void kernel_launch(void* const* d_in, const int* in_sizes, int n_in,
                              void* d_out, int out_size)
{
    const float* x     = (const float*)d_in[0];
    const float* W_enc = (const float*)d_in[1];
    const float* b_enc = (const float*)d_in[2];
    const float* W_dec = (const float*)d_in[3];
    const float* b_dec = (const float*)d_in[4];

    float* recon = (float*)d_out;
    float* feat  = (float*)d_out + (size_t)N_TOKENS * D_IN;

    cudaFuncSetAttribute(encode_mma_kernel,
                         cudaFuncAttributeMaxDynamicSharedMemorySize, ENC_SMEM);

    split_x_kernel<<<(N_TOKENS * D_IN) / 1024, 256>>>(x);
    split_w_kernel<<<((size_t)D_HIDDEN * D_IN) / 1024, 256>>>(W_enc);
    transpose_kernel<<<dim3(D_HIDDEN / 32, D_IN / 32), dim3(32, 8)>>>(W_dec);

    encode_mma_kernel<<<dim3(N_TOKENS / 128, D_HIDDEN / 128), 256, ENC_SMEM>>>(b_enc, feat);

    topk_kernel<<<N_TOKENS, 256>>>(feat);
    rerank_kernel<<<N_TOKENS, 256>>>(x, W_enc, b_enc, feat);
    decode_kernel<<<N_TOKENS, 256>>>(recon, b_dec);
}

// round 6
// speedup vs baseline: 15.5659x; 1.3276x over previous
#include <cuda_runtime.h>
#include <cuda_fp16.h>
#include <cstdint>

#define N_TOKENS 4096
#define D_IN     4096
#define D_HIDDEN 32768
#define TOPK     64
#define MARGIN   2e-3f

// ---------------- device scratch (no allocations allowed) -------------------
__device__ __half g_x1[(size_t)N_TOKENS * D_IN];
__device__ __half g_x2[(size_t)N_TOKENS * D_IN];
__device__ __half g_w1[(size_t)D_HIDDEN * D_IN];
__device__ float g_wdecT[(size_t)D_HIDDEN * D_IN];
__device__ int   g_topk_idx[N_TOKENS * TOPK];
__device__ float g_topk_val[N_TOKENS * TOPK];
__device__ int   g_cand_idx[N_TOKENS * 64];
__device__ float g_cand_val[N_TOKENS * 64];
__device__ int   g_ndef[N_TOKENS];
__device__ int   g_ncand[N_TOKENS];

// ---------------- helpers ----------------------------------------------------
__device__ __forceinline__ uint32_t smem_u32(const void* p) {
    uint32_t a;
    asm("{ .reg .u64 t; cvta.to.shared.u64 t, %1; cvt.u32.u64 %0, t; }" : "=r"(a) : "l"(p));
    return a;
}
__device__ __forceinline__ void cp16(uint32_t saddr, const void* gaddr) {
    asm volatile("cp.async.cg.shared.global [%0], [%1], 16;" :: "r"(saddr), "l"(gaddr));
}
#define CP_COMMIT()  asm volatile("cp.async.commit_group;" ::: "memory")
#define CP_WAIT0()   asm volatile("cp.async.wait_group 0;" ::: "memory")
#define CP_WAIT1()   asm volatile("cp.async.wait_group 1;" ::: "memory")

#define LDSM_X4(d, addr) \
    asm volatile("ldmatrix.sync.aligned.m8n8.x4.shared.b16 {%0,%1,%2,%3}, [%4];" \
        : "=r"((d)[0]), "=r"((d)[1]), "=r"((d)[2]), "=r"((d)[3]) : "r"(addr))
#define LDSM_X2(d, addr) \
    asm volatile("ldmatrix.sync.aligned.m8n8.x2.shared.b16 {%0,%1}, [%2];" \
        : "=r"((d)[0]), "=r"((d)[1]) : "r"(addr))

__device__ __forceinline__ void mma16816(float* d, const uint32_t* a, const uint32_t* b) {
    asm volatile("mma.sync.aligned.m16n8k16.row.col.f32.f16.f16.f32 "
        "{%0,%1,%2,%3}, {%4,%5,%6,%7}, {%8,%9}, {%0,%1,%2,%3};"
        : "+f"(d[0]), "+f"(d[1]), "+f"(d[2]), "+f"(d[3])
        : "r"(a[0]), "r"(a[1]), "r"(a[2]), "r"(a[3]), "r"(b[0]), "r"(b[1]));
}

// ---------------- split kernels ---------------------------------------------
// x -> fp16 hi (x1) + fp16 residual (x2): 22 mantissa bits of x preserved.
__global__ __launch_bounds__(256)
void split_x_kernel(const float* __restrict__ src)
{
    size_t i = ((size_t)blockIdx.x * 256 + threadIdx.x) * 4;
    if (i >= (size_t)N_TOKENS * D_IN) return;
    float4 v = *(const float4*)(src + i);
    float f[4] = {v.x, v.y, v.z, v.w};
    __half h1[4], h2[4];
#pragma unroll
    for (int j = 0; j < 4; ++j) {
        h1[j] = __float2half_rn(f[j]);
        h2[j] = __float2half_rn(f[j] - __half2float(h1[j]));
    }
    *(__half2*)(g_x1 + i)     = __half2{h1[0], h1[1]};
    *(__half2*)(g_x1 + i + 2) = __half2{h1[2], h1[3]};
    *(__half2*)(g_x2 + i)     = __half2{h2[0], h2[1]};
    *(__half2*)(g_x2 + i + 2) = __half2{h2[2], h2[3]};
}

// W_enc -> single fp16 (dropped residual handled by MARGIN + exact rerank)
__global__ __launch_bounds__(256)
void split_w_kernel(const float* __restrict__ src)
{
    size_t i = ((size_t)blockIdx.x * 256 + threadIdx.x) * 4;
    if (i >= (size_t)D_HIDDEN * D_IN) return;
    float4 v = *(const float4*)(src + i);
    *(__half2*)(g_w1 + i)     = __half2{__float2half_rn(v.x), __float2half_rn(v.y)};
    *(__half2*)(g_w1 + i + 2) = __half2{__float2half_rn(v.z), __float2half_rn(v.w)};
}

// ---------------- encode: fp16 (x1+x2)*w1 GEMM on mma.sync ------------------
// CTA tile 128(tok) x 128(hid), BK=64, 8 warps 2x4, warp tile 64x32.
// SMEM stage: X1|X2|W (3 x 16KB, XOR chunk swizzle), 3-stage cp.async pipeline.
#define EBK 64
#define ARR_BYTES 16384
#define STAGE_BYTES (3 * ARR_BYTES)      // 48KB
#define ENC_SMEM (3 * STAGE_BYTES)       // 144KB
#define N_STAGES (D_IN / EBK)            // 64

__global__ __launch_bounds__(256, 1)
void encode_mma_kernel(const float* __restrict__ bias, float* __restrict__ feat)
{
    extern __shared__ __align__(128) char smem[];
    const int tid  = threadIdx.x;
    const int wid  = tid >> 5;
    const int lane = tid & 31;
    const int wm   = wid >> 2;       // 0..1
    const int wn   = wid & 3;        // 0..3
    const int bn   = blockIdx.x * 128;   // token tile (fastest -> B tile L2-hot)
    const int bh   = blockIdx.y * 128;   // hidden tile
    const uint32_t smem_base = smem_u32(smem);

    float acc[4][4][4];
#pragma unroll
    for (int mt = 0; mt < 4; ++mt)
#pragma unroll
        for (int nt = 0; nt < 4; ++nt)
#pragma unroll
            for (int q = 0; q < 4; ++q) acc[mt][nt][q] = 0.0f;

#define PREFETCH(s) do {                                                          \
    const int _k0 = (s) * EBK;                                                    \
    const uint32_t _st = smem_base + ((s) % 3) * STAGE_BYTES;                     \
    _Pragma("unroll")                                                             \
    for (int _l = 0; _l < 4; ++_l) {                                              \
        int _id = _l * 256 + tid;                                                 \
        int _r = _id >> 3, _c = _id & 7;                                          \
        uint32_t _sw = (uint32_t)(_r * 128 + ((_c ^ (_r & 7)) << 4));             \
        size_t _ga = (size_t)(bn + _r) * D_IN + _k0 + _c * 8;                     \
        size_t _gb = (size_t)(bh + _r) * D_IN + _k0 + _c * 8;                     \
        cp16(_st + 0 * ARR_BYTES + _sw, g_x1 + _ga);                              \
        cp16(_st + 1 * ARR_BYTES + _sw, g_x2 + _ga);                              \
        cp16(_st + 2 * ARR_BYTES + _sw, g_w1 + _gb);                              \
    }                                                                             \
    CP_COMMIT();                                                                  \
} while (0)

    PREFETCH(0);
    PREFETCH(1);

    const int rA_base = wm * 64 + (lane & 15);
    const int rB_base = wn * 32 + (lane & 7);

    for (int s = 0; s < N_STAGES; ++s) {
        if (s + 2 < N_STAGES) {
            CP_WAIT1();
            __syncthreads();
            PREFETCH(s + 2);
        } else {
            CP_WAIT0();
            __syncthreads();
        }
        const uint32_t st = smem_base + (s % 3) * STAGE_BYTES;

#pragma unroll
        for (int ks = 0; ks < 4; ++ks) {
            uint32_t a1[4][4], a2[4][4], b[4][2];
            const int cA = 2 * ks + (lane >> 4);
#pragma unroll
            for (int mt = 0; mt < 4; ++mt) {
                int r = rA_base + mt * 16;
                uint32_t off = st + (uint32_t)(r * 128 + ((cA ^ (r & 7)) << 4));
                LDSM_X4(a1[mt], off + 0 * ARR_BYTES);
                LDSM_X4(a2[mt], off + 1 * ARR_BYTES);
            }
            const int cB = 2 * ks + ((lane >> 3) & 1);
#pragma unroll
            for (int nt = 0; nt < 4; ++nt) {
                int r = rB_base + nt * 8;
                uint32_t off = st + (uint32_t)(r * 128 + ((cB ^ (r & 7)) << 4));
                LDSM_X2(b[nt], off + 2 * ARR_BYTES);
            }
#pragma unroll
            for (int mt = 0; mt < 4; ++mt) {
#pragma unroll
                for (int nt = 0; nt < 4; ++nt) {
                    mma16816(acc[mt][nt], a1[mt], b[nt]);
                    mma16816(acc[mt][nt], a2[mt], b[nt]);
                }
            }
        }
        __syncthreads();
    }
#undef PREFETCH

    // Epilogue: +bias, ReLU, store fp32
#pragma unroll
    for (int mt = 0; mt < 4; ++mt) {
        const int row0 = bn + wm * 64 + mt * 16 + (lane >> 2);
#pragma unroll
        for (int nt = 0; nt < 4; ++nt) {
            const int col0 = bh + wn * 32 + nt * 8 + (lane & 3) * 2;
            const float bb0 = bias[col0], bb1 = bias[col0 + 1];
            float2 v0, v1;
            v0.x = acc[mt][nt][0] + bb0; v0.x = v0.x > 0.0f ? v0.x : 0.0f;
            v0.y = acc[mt][nt][1] + bb1; v0.y = v0.y > 0.0f ? v0.y : 0.0f;
            v1.x = acc[mt][nt][2] + bb0; v1.x = v1.x > 0.0f ? v1.x : 0.0f;
            v1.y = acc[mt][nt][3] + bb1; v1.y = v1.y > 0.0f ? v1.y : 0.0f;
            *(float2*)&feat[(size_t)row0 * D_HIDDEN + col0]       = v0;
            *(float2*)&feat[(size_t)(row0 + 8) * D_HIDDEN + col0] = v1;
        }
    }
}

// ---------------- top-k: 1-pass linear histogram + margin classify ----------
// 4096 bins over [0,8) (width 1/512 ~ 2e-3). The 64th value's bin gives thr
// within the bin width; margin classification + exact rerank absorb both the
// bin quantization and the GEMM approximation error.
__global__ __launch_bounds__(256)
void topk_kernel(float* __restrict__ feat)
{
    const int n   = blockIdx.x;
    const int tid = threadIdx.x;
    float* row = feat + (size_t)n * D_HIDDEN;

    __shared__ int hist[4096];
    __shared__ int s_part[256];
    __shared__ int s_bin;
    __shared__ int s_ndef, s_ncand;

    for (int i = tid; i < 4096; i += 256) hist[i] = 0;
    if (tid == 0) { s_bin = 0; s_ndef = 0; s_ncand = 0; }
    __syncthreads();

    for (int i = tid; i < D_HIDDEN; i += 256) {
        float v = row[i];
        if (v > 0.0f) {
            int b = (int)(v * 512.0f);
            if (b > 4095) b = 4095;
            atomicAdd(&hist[b], 1);
        }
    }
    __syncthreads();

    // suffix sums from the top: thread t covers bins [4095-16t-15, 4095-16t]
    const int hi_b = 4095 - tid * 16;
    int part = 0;
#pragma unroll
    for (int j = 0; j < 16; ++j) part += hist[hi_b - j];
    s_part[tid] = part;
    __syncthreads();
    for (int off = 1; off < 256; off <<= 1) {
        int v2 = (tid >= off) ? s_part[tid - off] : 0;
        __syncthreads();
        s_part[tid] += v2;
        __syncthreads();
    }
    const int incl = s_part[tid];
    const int excl = incl - part;
    if (excl < TOPK && incl >= TOPK) {
        int cum = excl;
        for (int j = 0; j < 16; ++j) {
            cum += hist[hi_b - j];
            if (cum >= TOPK) { s_bin = hi_b - j; break; }
        }
    }
    __syncthreads();

    const float lo = (float)s_bin / 512.0f - MARGIN;
    const float hi = (float)(s_bin + 1) / 512.0f + MARGIN;

    for (int i = tid; i < D_HIDDEN; i += 256) {
        float v = row[i];
        if (v > hi) {
            int p = atomicAdd(&s_ndef, 1);
            g_topk_idx[n * TOPK + p] = i;
            g_topk_val[n * TOPK + p] = v;
        } else {
            if (v >= lo) {
                int q = atomicAdd(&s_ncand, 1);
                if (q < 64) { g_cand_idx[n * 64 + q] = i; g_cand_val[n * 64 + q] = v; }
            }
            row[i] = 0.0f;
        }
    }
    __syncthreads();
    if (tid == 0) {
        g_ndef[n]  = s_ndef;
        g_ncand[n] = s_ncand < 64 ? s_ncand : 64;
    }
}

// ---------------- rerank: exact fp64 scoring of boundary candidates ---------
__global__ __launch_bounds__(256)
void rerank_kernel(const float* __restrict__ x, const float* __restrict__ W_enc,
                   const float* __restrict__ b_enc, float* __restrict__ feat)
{
    __shared__ float  sx[D_IN];
    __shared__ double sred[256];
    __shared__ double s_exact[64];

    const int n   = blockIdx.x;
    const int tid = threadIdx.x;
    const int ndef  = g_ndef[n];
    const int ncand = g_ncand[n];
    const int need  = TOPK - ndef;
    float* row = feat + (size_t)n * D_HIDDEN;

    if (need <= 0) return;

    if (ncand <= need) {
        for (int c = tid; c < ncand; c += 256) {
            int idx = g_cand_idx[n * 64 + c];
            float v = g_cand_val[n * 64 + c];
            row[idx] = v;
            g_topk_idx[n * TOPK + ndef + c] = idx;
            g_topk_val[n * TOPK + ndef + c] = v;
        }
        return;
    }

    for (int i = tid * 4; i < D_IN; i += 1024)
        *(float4*)&sx[i] = *(const float4*)(x + (size_t)n * D_IN + i);
    __syncthreads();

    for (int c = 0; c < ncand; ++c) {
        const float* w = W_enc + (size_t)g_cand_idx[n * 64 + c] * D_IN;
        double acc = 0.0;
        for (int j = tid; j < D_IN; j += 256)
            acc += (double)sx[j] * (double)w[j];
        sred[tid] = acc;
        __syncthreads();
        for (int st = 128; st > 0; st >>= 1) {
            if (tid < st) sred[tid] += sred[tid + st];
            __syncthreads();
        }
        if (tid == 0) {
            double v = sred[0] + (double)b_enc[g_cand_idx[n * 64 + c]];
            s_exact[c] = v > 0.0 ? v : 0.0;
        }
        __syncthreads();
    }

    if (tid == 0) {
        bool used[64];
        for (int c = 0; c < ncand; ++c) used[c] = false;
        for (int r = 0; r < need; ++r) {
            int best = -1;
            for (int c = 0; c < ncand; ++c) {
                if (used[c]) continue;
                if (best < 0 || s_exact[c] > s_exact[best] ||
                    (s_exact[c] == s_exact[best] &&
                     g_cand_idx[n * 64 + c] < g_cand_idx[n * 64 + best]))
                    best = c;
            }
            used[best] = true;
            int idx = g_cand_idx[n * 64 + best];
            float v = g_cand_val[n * 64 + best];
            row[idx] = v;
            g_topk_idx[n * TOPK + ndef + r] = idx;
            g_topk_val[n * TOPK + ndef + r] = v;
        }
    }
}

// ---------------- transpose W_dec -> [h][d] ---------------------------------
__global__ __launch_bounds__(256)
void transpose_kernel(const float* __restrict__ W)
{
    __shared__ float t[32][33];
    const int h0 = blockIdx.x * 32;
    const int d0 = blockIdx.y * 32;
    const int tx = threadIdx.x;
    const int ty = threadIdx.y;
#pragma unroll
    for (int i = 0; i < 32; i += 8)
        t[ty + i][tx] = W[(size_t)(d0 + ty + i) * D_HIDDEN + h0 + tx];
    __syncthreads();
#pragma unroll
    for (int i = 0; i < 32; i += 8)
        g_wdecT[(size_t)(h0 + ty + i) * D_IN + d0 + tx] = t[tx][ty + i];
}

// ---------------- sparse decode ---------------------------------------------
__global__ __launch_bounds__(256)
void decode_kernel(float* __restrict__ recon, const float* __restrict__ b_dec)
{
    const int n   = blockIdx.x;
    const int tid = threadIdx.x;

    __shared__ int   s_idx[TOPK];
    __shared__ float s_val[TOPK];
    if (tid < TOPK) {
        s_idx[tid] = g_topk_idx[n * TOPK + tid];
        s_val[tid] = g_topk_val[n * TOPK + tid];
    }
    __syncthreads();

    float acc[16];
#pragma unroll
    for (int r = 0; r < 16; ++r) acc[r] = b_dec[tid + r * 256];

    for (int j = 0; j < TOPK; ++j) {
        const float* wr = g_wdecT + (size_t)s_idx[j] * D_IN;
        const float  v  = s_val[j];
#pragma unroll
        for (int r = 0; r < 16; ++r)
            acc[r] += v * wr[tid + r * 256];
    }

    float* out = recon + (size_t)n * D_IN;
#pragma unroll
    for (int r = 0; r < 16; ++r) out[tid + r * 256] = acc[r];
}

// ---------------- launch -----------------------------------------------------
extern "C" void kernel_launch(void* const* d_in, const int* in_sizes, int n_in,
                              void* d_out, int out_size)
{
    const float* x     = (const float*)d_in[0];
    const float* W_enc = (const float*)d_in[1];
    const float* b_enc = (const float*)d_in[2];
    const float* W_dec = (const float*)d_in[3];
    const float* b_dec = (const float*)d_in[4];

    float* recon = (float*)d_out;
    float* feat  = (float*)d_out + (size_t)N_TOKENS * D_IN;

    cudaFuncSetAttribute(encode_mma_kernel,
                         cudaFuncAttributeMaxDynamicSharedMemorySize, ENC_SMEM);

    split_x_kernel<<<(N_TOKENS * D_IN) / 1024, 256>>>(x);
    split_w_kernel<<<((size_t)D_HIDDEN * D_IN) / 1024, 256>>>(W_enc);
    transpose_kernel<<<dim3(D_HIDDEN / 32, D_IN / 32), dim3(32, 8)>>>(W_dec);

    encode_mma_kernel<<<dim3(N_TOKENS / 128, D_HIDDEN / 128), 256, ENC_SMEM>>>(b_enc, feat);

    topk_kernel<<<N_TOKENS, 256>>>(feat);
    rerank_kernel<<<N_TOKENS, 256>>>(x, W_enc, b_enc, feat);
    decode_kernel<<<N_TOKENS, 256>>>(recon, b_dec);
}

// round 7
// speedup vs baseline: 25.1962x; 1.6187x over previous
#include <cuda_runtime.h>
#include <cuda_fp16.h>
#include <cstdint>

#define N_TOKENS 4096
#define D_IN     4096
#define D_HIDDEN 32768
#define TOPK     64
#define MARGIN   5e-3f

// ---------------- device scratch (no allocations allowed) -------------------
__device__ __half g_x1[(size_t)N_TOKENS * D_IN];
__device__ __half g_w1[(size_t)D_HIDDEN * D_IN];
__device__ float g_wdecT[(size_t)D_HIDDEN * D_IN];
__device__ int   g_topk_idx[N_TOKENS * TOPK];
__device__ float g_topk_val[N_TOKENS * TOPK];
__device__ int   g_cand_idx[N_TOKENS * 64];
__device__ float g_cand_val[N_TOKENS * 64];
__device__ int   g_ndef[N_TOKENS];
__device__ int   g_ncand[N_TOKENS];

// ---------------- helpers ----------------------------------------------------
__device__ __forceinline__ uint32_t smem_u32(const void* p) {
    uint32_t a;
    asm("{ .reg .u64 t; cvta.to.shared.u64 t, %1; cvt.u32.u64 %0, t; }" : "=r"(a) : "l"(p));
    return a;
}
__device__ __forceinline__ void cp16(uint32_t saddr, const void* gaddr) {
    asm volatile("cp.async.cg.shared.global [%0], [%1], 16;" :: "r"(saddr), "l"(gaddr));
}
#define CP_COMMIT()  asm volatile("cp.async.commit_group;" ::: "memory")
#define CP_WAIT0()   asm volatile("cp.async.wait_group 0;" ::: "memory")
#define CP_WAIT1()   asm volatile("cp.async.wait_group 1;" ::: "memory")

#define LDSM_X4(d, addr) \
    asm volatile("ldmatrix.sync.aligned.m8n8.x4.shared.b16 {%0,%1,%2,%3}, [%4];" \
        : "=r"((d)[0]), "=r"((d)[1]), "=r"((d)[2]), "=r"((d)[3]) : "r"(addr))
#define LDSM_X2(d, addr) \
    asm volatile("ldmatrix.sync.aligned.m8n8.x2.shared.b16 {%0,%1}, [%2];" \
        : "=r"((d)[0]), "=r"((d)[1]) : "r"(addr))

__device__ __forceinline__ void mma16816(float* d, const uint32_t* a, const uint32_t* b) {
    asm volatile("mma.sync.aligned.m16n8k16.row.col.f32.f16.f16.f32 "
        "{%0,%1,%2,%3}, {%4,%5,%6,%7}, {%8,%9}, {%0,%1,%2,%3};"
        : "+f"(d[0]), "+f"(d[1]), "+f"(d[2]), "+f"(d[3])
        : "r"(a[0]), "r"(a[1]), "r"(a[2]), "r"(a[3]), "r"(b[0]), "r"(b[1]));
}

// ---------------- convert kernels (fp32 -> fp16) ----------------------------
__global__ __launch_bounds__(256)
void split_x_kernel(const float* __restrict__ src)
{
    size_t i = ((size_t)blockIdx.x * 256 + threadIdx.x) * 4;
    if (i >= (size_t)N_TOKENS * D_IN) return;
    float4 v = *(const float4*)(src + i);
    *(__half2*)(g_x1 + i)     = __half2{__float2half_rn(v.x), __float2half_rn(v.y)};
    *(__half2*)(g_x1 + i + 2) = __half2{__float2half_rn(v.z), __float2half_rn(v.w)};
}

__global__ __launch_bounds__(256)
void split_w_kernel(const float* __restrict__ src)
{
    size_t i = ((size_t)blockIdx.x * 256 + threadIdx.x) * 4;
    if (i >= (size_t)D_HIDDEN * D_IN) return;
    float4 v = *(const float4*)(src + i);
    *(__half2*)(g_w1 + i)     = __half2{__float2half_rn(v.x), __float2half_rn(v.y)};
    *(__half2*)(g_w1 + i + 2) = __half2{__float2half_rn(v.z), __float2half_rn(v.w)};
}

// ---------------- encode: fp16 x*w GEMM on mma.sync -------------------------
// CTA tile 128(tok) x 128(hid), BK=64, 8 warps 2x4, warp tile 64x32.
// SMEM stage: X|W (2 x 16KB, XOR chunk swizzle), 3-stage cp.async pipeline,
// 96KB smem -> 2 CTAs/SM (launch_bounds caps regs at 128).
#define EBK 64
#define ARR_BYTES 16384
#define STAGE_BYTES (2 * ARR_BYTES)      // 32KB
#define ENC_SMEM (3 * STAGE_BYTES)       // 96KB
#define N_STAGES (D_IN / EBK)            // 64

__global__ __launch_bounds__(256, 2)
void encode_mma_kernel(const float* __restrict__ bias, float* __restrict__ feat)
{
    extern __shared__ __align__(128) char smem[];
    const int tid  = threadIdx.x;
    const int wid  = tid >> 5;
    const int lane = tid & 31;
    const int wm   = wid >> 2;       // 0..1
    const int wn   = wid & 3;        // 0..3
    const int bn   = blockIdx.x * 128;   // token tile (fastest -> B tile L2-hot)
    const int bh   = blockIdx.y * 128;   // hidden tile
    const uint32_t smem_base = smem_u32(smem);

    float acc[4][4][4];
#pragma unroll
    for (int mt = 0; mt < 4; ++mt)
#pragma unroll
        for (int nt = 0; nt < 4; ++nt)
#pragma unroll
            for (int q = 0; q < 4; ++q) acc[mt][nt][q] = 0.0f;

#define PREFETCH(s) do {                                                          \
    const int _k0 = (s) * EBK;                                                    \
    const uint32_t _st = smem_base + ((s) % 3) * STAGE_BYTES;                     \
    _Pragma("unroll")                                                             \
    for (int _l = 0; _l < 4; ++_l) {                                              \
        int _id = _l * 256 + tid;                                                 \
        int _r = _id >> 3, _c = _id & 7;                                          \
        uint32_t _sw = (uint32_t)(_r * 128 + ((_c ^ (_r & 7)) << 4));             \
        size_t _ga = (size_t)(bn + _r) * D_IN + _k0 + _c * 8;                     \
        size_t _gb = (size_t)(bh + _r) * D_IN + _k0 + _c * 8;                     \
        cp16(_st + 0 * ARR_BYTES + _sw, g_x1 + _ga);                              \
        cp16(_st + 1 * ARR_BYTES + _sw, g_w1 + _gb);                              \
    }                                                                             \
    CP_COMMIT();                                                                  \
} while (0)

    PREFETCH(0);
    PREFETCH(1);

    const int rA_base = wm * 64 + (lane & 15);
    const int rB_base = wn * 32 + (lane & 7);

    for (int s = 0; s < N_STAGES; ++s) {
        if (s + 2 < N_STAGES) {
            CP_WAIT1();
            __syncthreads();
            PREFETCH(s + 2);
        } else {
            CP_WAIT0();
            __syncthreads();
        }
        const uint32_t st = smem_base + (s % 3) * STAGE_BYTES;

#pragma unroll
        for (int ks = 0; ks < 4; ++ks) {
            uint32_t a[4][4], b[4][2];
            const int cA = 2 * ks + (lane >> 4);
#pragma unroll
            for (int mt = 0; mt < 4; ++mt) {
                int r = rA_base + mt * 16;
                uint32_t off = st + (uint32_t)(r * 128 + ((cA ^ (r & 7)) << 4));
                LDSM_X4(a[mt], off + 0 * ARR_BYTES);
            }
            const int cB = 2 * ks + ((lane >> 3) & 1);
#pragma unroll
            for (int nt = 0; nt < 4; ++nt) {
                int r = rB_base + nt * 8;
                uint32_t off = st + (uint32_t)(r * 128 + ((cB ^ (r & 7)) << 4));
                LDSM_X2(b[nt], off + 1 * ARR_BYTES);
            }
#pragma unroll
            for (int mt = 0; mt < 4; ++mt)
#pragma unroll
                for (int nt = 0; nt < 4; ++nt)
                    mma16816(acc[mt][nt], a[mt], b[nt]);
        }
        __syncthreads();
    }
#undef PREFETCH

    // Epilogue: +bias, ReLU, store fp32
#pragma unroll
    for (int mt = 0; mt < 4; ++mt) {
        const int row0 = bn + wm * 64 + mt * 16 + (lane >> 2);
#pragma unroll
        for (int nt = 0; nt < 4; ++nt) {
            const int col0 = bh + wn * 32 + nt * 8 + (lane & 3) * 2;
            const float bb0 = bias[col0], bb1 = bias[col0 + 1];
            float2 v0, v1;
            v0.x = acc[mt][nt][0] + bb0; v0.x = v0.x > 0.0f ? v0.x : 0.0f;
            v0.y = acc[mt][nt][1] + bb1; v0.y = v0.y > 0.0f ? v0.y : 0.0f;
            v1.x = acc[mt][nt][2] + bb0; v1.x = v1.x > 0.0f ? v1.x : 0.0f;
            v1.y = acc[mt][nt][3] + bb1; v1.y = v1.y > 0.0f ? v1.y : 0.0f;
            *(float2*)&feat[(size_t)row0 * D_HIDDEN + col0]       = v0;
            *(float2*)&feat[(size_t)(row0 + 8) * D_HIDDEN + col0] = v1;
        }
    }
}

// ---------------- top-k: 1-pass linear histogram + margin classify ----------
// 4096 bins over [0,8). Margin classification + exact fp64 rerank absorb both
// the bin quantization and the fp16 GEMM approximation error.
__global__ __launch_bounds__(256)
void topk_kernel(float* __restrict__ feat)
{
    const int n   = blockIdx.x;
    const int tid = threadIdx.x;
    float* row = feat + (size_t)n * D_HIDDEN;

    __shared__ int hist[4096];
    __shared__ int s_part[256];
    __shared__ int s_bin;
    __shared__ int s_ndef, s_ncand;

    for (int i = tid; i < 4096; i += 256) hist[i] = 0;
    if (tid == 0) { s_bin = 0; s_ndef = 0; s_ncand = 0; }
    __syncthreads();

    for (int i = tid; i < D_HIDDEN; i += 256) {
        float v = row[i];
        if (v > 0.0f) {
            int b = (int)(v * 512.0f);
            if (b > 4095) b = 4095;
            atomicAdd(&hist[b], 1);
        }
    }
    __syncthreads();

    const int hi_b = 4095 - tid * 16;
    int part = 0;
#pragma unroll
    for (int j = 0; j < 16; ++j) part += hist[hi_b - j];
    s_part[tid] = part;
    __syncthreads();
    for (int off = 1; off < 256; off <<= 1) {
        int v2 = (tid >= off) ? s_part[tid - off] : 0;
        __syncthreads();
        s_part[tid] += v2;
        __syncthreads();
    }
    const int incl = s_part[tid];
    const int excl = incl - part;
    if (excl < TOPK && incl >= TOPK) {
        int cum = excl;
        for (int j = 0; j < 16; ++j) {
            cum += hist[hi_b - j];
            if (cum >= TOPK) { s_bin = hi_b - j; break; }
        }
    }
    __syncthreads();

    const float lo = (float)s_bin / 512.0f - MARGIN;
    const float hi = (float)(s_bin + 1) / 512.0f + MARGIN;

    for (int i = tid; i < D_HIDDEN; i += 256) {
        float v = row[i];
        if (v > hi) {
            int p = atomicAdd(&s_ndef, 1);
            g_topk_idx[n * TOPK + p] = i;
            g_topk_val[n * TOPK + p] = v;
        } else {
            if (v >= lo) {
                int q = atomicAdd(&s_ncand, 1);
                if (q < 64) { g_cand_idx[n * 64 + q] = i; g_cand_val[n * 64 + q] = v; }
            }
            row[i] = 0.0f;
        }
    }
    __syncthreads();
    if (tid == 0) {
        g_ndef[n]  = s_ndef;
        g_ncand[n] = s_ncand < 64 ? s_ncand : 64;
    }
}

// ---------------- rerank: exact fp64 scoring of boundary candidates ---------
__global__ __launch_bounds__(256)
void rerank_kernel(const float* __restrict__ x, const float* __restrict__ W_enc,
                   const float* __restrict__ b_enc, float* __restrict__ feat)
{
    __shared__ float  sx[D_IN];
    __shared__ double sred[256];
    __shared__ double s_exact[64];

    const int n   = blockIdx.x;
    const int tid = threadIdx.x;
    const int ndef  = g_ndef[n];
    const int ncand = g_ncand[n];
    const int need  = TOPK - ndef;
    float* row = feat + (size_t)n * D_HIDDEN;

    if (need <= 0) return;

    if (ncand <= need) {
        for (int c = tid; c < ncand; c += 256) {
            int idx = g_cand_idx[n * 64 + c];
            float v = g_cand_val[n * 64 + c];
            row[idx] = v;
            g_topk_idx[n * TOPK + ndef + c] = idx;
            g_topk_val[n * TOPK + ndef + c] = v;
        }
        return;
    }

    for (int i = tid * 4; i < D_IN; i += 1024)
        *(float4*)&sx[i] = *(const float4*)(x + (size_t)n * D_IN + i);
    __syncthreads();

    for (int c = 0; c < ncand; ++c) {
        const float* w = W_enc + (size_t)g_cand_idx[n * 64 + c] * D_IN;
        double acc = 0.0;
        for (int j = tid; j < D_IN; j += 256)
            acc += (double)sx[j] * (double)w[j];
        sred[tid] = acc;
        __syncthreads();
        for (int st = 128; st > 0; st >>= 1) {
            if (tid < st) sred[tid] += sred[tid + st];
            __syncthreads();
        }
        if (tid == 0) {
            double v = sred[0] + (double)b_enc[g_cand_idx[n * 64 + c]];
            s_exact[c] = v > 0.0 ? v : 0.0;
        }
        __syncthreads();
    }

    if (tid == 0) {
        bool used[64];
        for (int c = 0; c < ncand; ++c) used[c] = false;
        for (int r = 0; r < need; ++r) {
            int best = -1;
            for (int c = 0; c < ncand; ++c) {
                if (used[c]) continue;
                if (best < 0 || s_exact[c] > s_exact[best] ||
                    (s_exact[c] == s_exact[best] &&
                     g_cand_idx[n * 64 + c] < g_cand_idx[n * 64 + best]))
                    best = c;
            }
            used[best] = true;
            int idx = g_cand_idx[n * 64 + best];
            float v = g_cand_val[n * 64 + best];
            row[idx] = v;
            g_topk_idx[n * TOPK + ndef + r] = idx;
            g_topk_val[n * TOPK + ndef + r] = v;
        }
    }
}

// ---------------- transpose W_dec -> [h][d] ---------------------------------
__global__ __launch_bounds__(256)
void transpose_kernel(const float* __restrict__ W)
{
    __shared__ float t[32][33];
    const int h0 = blockIdx.x * 32;
    const int d0 = blockIdx.y * 32;
    const int tx = threadIdx.x;
    const int ty = threadIdx.y;
#pragma unroll
    for (int i = 0; i < 32; i += 8)
        t[ty + i][tx] = W[(size_t)(d0 + ty + i) * D_HIDDEN + h0 + tx];
    __syncthreads();
#pragma unroll
    for (int i = 0; i < 32; i += 8)
        g_wdecT[(size_t)(h0 + ty + i) * D_IN + d0 + tx] = t[tx][ty + i];
}

// ---------------- sparse decode ---------------------------------------------
__global__ __launch_bounds__(256)
void decode_kernel(float* __restrict__ recon, const float* __restrict__ b_dec)
{
    const int n   = blockIdx.x;
    const int tid = threadIdx.x;

    __shared__ int   s_idx[TOPK];
    __shared__ float s_val[TOPK];
    if (tid < TOPK) {
        s_idx[tid] = g_topk_idx[n * TOPK + tid];
        s_val[tid] = g_topk_val[n * TOPK + tid];
    }
    __syncthreads();

    float acc[16];
#pragma unroll
    for (int r = 0; r < 16; ++r) acc[r] = b_dec[tid + r * 256];

    for (int j = 0; j < TOPK; ++j) {
        const float* wr = g_wdecT + (size_t)s_idx[j] * D_IN;
        const float  v  = s_val[j];
#pragma unroll
        for (int r = 0; r < 16; ++r)
            acc[r] += v * wr[tid + r * 256];
    }

    float* out = recon + (size_t)n * D_IN;
#pragma unroll
    for (int r = 0; r < 16; ++r) out[tid + r * 256] = acc[r];
}

// ---------------- launch -----------------------------------------------------
extern "C" void kernel_launch(void* const* d_in, const int* in_sizes, int n_in,
                              void* d_out, int out_size)
{
    const float* x     = (const float*)d_in[0];
    const float* W_enc = (const float*)d_in[1];
    const float* b_enc = (const float*)d_in[2];
    const float* W_dec = (const float*)d_in[3];
    const float* b_dec = (const float*)d_in[4];

    float* recon = (float*)d_out;
    float* feat  = (float*)d_out + (size_t)N_TOKENS * D_IN;

    cudaFuncSetAttribute(encode_mma_kernel,
                         cudaFuncAttributeMaxDynamicSharedMemorySize, ENC_SMEM);

    split_x_kernel<<<(N_TOKENS * D_IN) / 1024, 256>>>(x);
    split_w_kernel<<<((size_t)D_HIDDEN * D_IN) / 1024, 256>>>(W_enc);
    transpose_kernel<<<dim3(D_HIDDEN / 32, D_IN / 32), dim3(32, 8)>>>(W_dec);

    encode_mma_kernel<<<dim3(N_TOKENS / 128, D_HIDDEN / 128), 256, ENC_SMEM>>>(b_enc, feat);

    topk_kernel<<<N_TOKENS, 256>>>(feat);
    rerank_kernel<<<N_TOKENS, 256>>>(x, W_enc, b_enc, feat);
    decode_kernel<<<N_TOKENS, 256>>>(recon, b_dec);
}